// round 10
// baseline (speedup 1.0000x reference)
#include <cuda_runtime.h>
#include <math.h>

#define KGRID 64
#define NRAY2 4096
#define NS    64
#define OUTN  192
#define OUT3  (OUTN*OUTN*OUTN)

#define RAY_BLOCKS   256                  // 16 rays/block at 128 threads
#define ZTILE        16
#define BUILD_BLOCKS (OUTN * (OUTN / ZTILE))   // 192 y * 12 ztiles = 2304

// ---------------- scratch ----------------
__device__ float4 gM4[NRAY2 * NS];   // mesh {2X-1, 2Y-1, 2z-1, _}
// z-FASTEST packed 2x2 taps: gVolP[((y*192)+x)*192 + z] =
//   {v[z][y][x], v[z][y][x+1], v[z][y+1][x], v[z][y+1][x+1]} (edge-replicated)
__device__ float4 gVolP[OUT3];

// ---------------- compile-time matrices ----------------
constexpr double c_sin(double x) {
    double x2 = x * x;
    return x * (1.0 + x2 * (-1.0/6.0 + x2 * (1.0/120.0 + x2 * (-1.0/5040.0
             + x2 * (1.0/362880.0 + x2 * (-1.0/39916800.0))))));
}
constexpr double c_cos(double x) {
    double x2 = x * x;
    return 1.0 + x2 * (-0.5 + x2 * (1.0/24.0 + x2 * (-1.0/720.0
             + x2 * (1.0/40320.0 + x2 * (-1.0/3628800.0 + x2 * (1.0/479001600.0))))));
}
struct M4m { double a[16]; };
constexpr M4m c_mul(const M4m& A, const M4m& B) {
    M4m C{};
    for (int i = 0; i < 4; i++)
        for (int j = 0; j < 4; j++) {
            double s = 0.0;
            for (int k = 0; k < 4; k++) s += A.a[i*4+k] * B.a[k*4+j];
            C.a[i*4+j] = s;
        }
    return C;
}
constexpr M4m c_ry(double t) { double c=c_cos(t), s=c_sin(t); return M4m{{1,0,0,0, 0,c,-s,0, 0,s,c,0, 0,0,0,1}}; }
constexpr M4m c_rx(double t) { double c=c_cos(t), s=c_sin(t); return M4m{{c,0,-s,0, 0,1,0,0, s,0,c,0, 0,0,0,1}}; }
constexpr M4m c_rz(double t) { double c=c_cos(t), s=c_sin(t); return M4m{{c,-s,0,0, s,c,0,0, 0,0,1,0, 0,0,0,1}}; }
struct Mats { float mc[12]; float md[12]; };
constexpr Mats build_mats() {
    const double TX = 0.1, TY = 0.05, TZ = 0.02, CX = 0.5;
    M4m RY  = c_ry(-TY), RY_ = c_ry( TY);
    M4m RX  = c_rx( TX), RX_ = c_rx(-TX);
    M4m RZ  = c_rz(-TZ), RZ_ = c_rz( TZ);
    M4m S1{{1,0,0,0, 0,1,0,0, 0,0,1,0, -CX,-CX,-CX,1}};
    M4m S2{{1,0,0,0, 0,1,0,0, 0,0,1,0,  CX, CX, CX,1}};
    M4m M_crd = c_mul(c_mul(c_mul(c_mul(S1, RZ), RY), RX), S2);
    M4m M_drv = c_mul(c_mul(RX_, RY_), RZ_);
    Mats r{};
    for (int i = 0; i < 4; i++)
        for (int j = 0; j < 3; j++) {
            r.mc[i*3+j] = (float)M_crd.a[i*4+j];
            r.md[i*3+j] = (float)M_drv.a[i*4+j];
        }
    return r;
}
__constant__ Mats cMat = build_mats();

// ---------------- ray-tracing body (R6 structure, proven) ----------------
__device__ __forceinline__ void ray_body(const float* __restrict__ RI,
                                         const float* __restrict__ ray0,
                                         int warp_global, int lane) {
    int grp  = (lane >> 3);
    int l    = lane & 7;
    int ray  = warp_global * 4 + grp;
    if (ray >= NRAY2) return;

    float mc[12], md[12];
#pragma unroll
    for (int i = 0; i < 12; i++) { mc[i] = cMat.mc[i]; md[i] = cMat.md[i]; }

    const float* r0 = ray0 + ray * 5;
    float X = r0[0], dX1 = r0[1], Y = r0[2], dY1 = r0[3], z = r0[4];

    float xr[4], yr[4], zr[4];
    bool  act[4];
#pragma unroll
    for (int k = 0; k < 4; k++) {
        int m = l + 8 * k;
        act[k] = (m < 27);
        int mm = act[k] ? m : 0;
        xr[k] = (float)((mm / 3) % 3 - 1);
        yr[k] = (float)(mm / 9 - 1);
        zr[k] = (float)(mm % 3 - 1);
    }

    const float2* ri2 = (const float2*)RI;
    const float STEP  = 1.0f / 63.0f;
    const float INV63 = 1.0f / 63.0f;

    if (l == 0)
        gM4[ray * NS] = make_float4(2.0f*X - 1.0f, 2.0f*Y - 1.0f, 2.0f*z - 1.0f, 0.0f);

    float cXv, cYv, cZv;
    float cfX[4], cfY[4], cfZ[4];
    float2 ri_cur[4];
    {
        float t0 = Y * mc[0] + X * mc[3] + z * mc[6] + mc[9];
        float t1 = Y * mc[1] + X * mc[4] + z * mc[7] + mc[10];
        float t2 = Y * mc[2] + X * mc[5] + z * mc[8] + mc[11];
        cXv = t1; cYv = t0; cZv = t2;
        float rX = rintf(cXv * 64.0f), rY = rintf(cYv * 64.0f), rZ = rintf(cZv * 64.0f);
#pragma unroll
        for (int k = 0; k < 4; k++) {
            cfX[k] = fminf(fmaxf(rX + xr[k], 0.0f), 63.0f);
            cfY[k] = fminf(fmaxf(rY + yr[k], 0.0f), 63.0f);
            cfZ[k] = fminf(fmaxf(rZ + zr[k], 0.0f), 63.0f);
            ri_cur[k] = make_float2(0.f, 1.f);
            if (act[k]) {
                int lin = ((int)cfY[k] << 12) + ((int)cfX[k] << 6) + (int)cfZ[k];
                ri_cur[k] = __ldg(&ri2[lin]);
            }
        }
    }

    for (int s = 1; s < NS; s++) {
        float Xn = X + dX1 * STEP;
        float Yn = Y + dY1 * STEP;
        float zn = z + STEP;

        float t0 = Yn * mc[0] + Xn * mc[3] + zn * mc[6] + mc[9];
        float t1 = Yn * mc[1] + Xn * mc[4] + zn * mc[7] + mc[10];
        float t2 = Yn * mc[2] + Xn * mc[5] + zn * mc[8] + mc[11];
        float nXv = t1, nYv = t0, nZv = t2;
        float rX = rintf(nXv * 64.0f), rY = rintf(nYv * 64.0f), rZ = rintf(nZv * 64.0f);
        float nfX[4], nfY[4], nfZ[4];
        float2 ri_next[4];
#pragma unroll
        for (int k = 0; k < 4; k++) {
            nfX[k] = fminf(fmaxf(rX + xr[k], 0.0f), 63.0f);
            nfY[k] = fminf(fmaxf(rY + yr[k], 0.0f), 63.0f);
            nfZ[k] = fminf(fmaxf(rZ + zr[k], 0.0f), 63.0f);
            ri_next[k] = make_float2(0.f, 1.f);
            if (act[k]) {
                int lin = ((int)nfY[k] << 12) + ((int)nfX[k] << 6) + (int)nfZ[k];
                ri_next[k] = __ldg(&ri2[lin]);
            }
        }

        float s_norm = 0.f, s_nus = 0.f, s_nx = 0.f, s_ny = 0.f,
              s_nz = 0.f, s_ndx = 0.f, s_ndy = 0.f, s_ndz = 0.f;
#pragma unroll
        for (int k = 0; k < 4; k++) {
            if (act[k]) {
                float dx  = cfX[k] * INV63 - cXv;
                float dy  = cfY[k] * INV63 - cYv;
                float dzv = cfZ[k] * INV63 - cZv;
                float A = ri_cur[k].x, sg = ri_cur[k].y;
                float inv_s2 = __fdividef(1.0f, sg * sg);
                float r2 = dx * dx + dy * dy + dzv * dzv;
                float ni = __expf(-r2 * 0.5f * inv_s2) + 2e-7f;
                float nu = ni * A;
                float hx = dx * inv_s2, hy = dy * inv_s2, hz = dzv * inv_s2;
                s_norm += ni;      s_nus += nu;
                s_nx += nu * hx;   s_ny += nu * hy;   s_nz += nu * hz;
                s_ndx += ni * hx;  s_ndy += ni * hy;  s_ndz += ni * hz;
            }
        }
#pragma unroll
        for (int off = 4; off > 0; off >>= 1) {
            s_norm += __shfl_xor_sync(0xffffffffu, s_norm, off);
            s_nus  += __shfl_xor_sync(0xffffffffu, s_nus,  off);
            s_nx   += __shfl_xor_sync(0xffffffffu, s_nx,   off);
            s_ny   += __shfl_xor_sync(0xffffffffu, s_ny,   off);
            s_nz   += __shfl_xor_sync(0xffffffffu, s_nz,   off);
            s_ndx  += __shfl_xor_sync(0xffffffffu, s_ndx,  off);
            s_ndy  += __shfl_xor_sync(0xffffffffu, s_ndy,  off);
            s_ndz  += __shfl_xor_sync(0xffffffffu, s_ndz,  off);
        }
        float inv_norm = __fdividef(1.0f, s_norm);
        float inv_n2 = inv_norm * inv_norm;
        float nx = (s_norm * s_nx - s_nus * s_ndx) * inv_n2;
        float ny = (s_norm * s_ny - s_nus * s_ndy) * inv_n2;
        float nz = (s_norm * s_nz - s_nus * s_ndz) * inv_n2;

        float d0 = ny * md[0] + nx * md[3] + nz * md[6] + md[9];
        float d1 = ny * md[1] + nx * md[4] + nz * md[7] + md[10];
        float d2 = ny * md[2] + nx * md[5] + nz * md[8] + md[11];
        float dndx = d1, dndz = d2, dndy = d0;

        float inv_n = __fdividef(s_norm, s_nus);
        float dX2 = (dndx - dndz * dX1) * (1.0f + dX1 * dX1) * inv_n;
        float dY2 = (dndy - dndz * dY1) * (1.0f + dY1 * dY1) * inv_n;

        dX1 += dX2 * STEP;
        dY1 += dY2 * STEP;
        X = Xn; Y = Yn; z = zn;

        if (l == 0)
            gM4[ray * NS + s] = make_float4(2.0f*X - 1.0f, 2.0f*Y - 1.0f, 2.0f*z - 1.0f, 0.0f);

        cXv = nXv; cYv = nYv; cZv = nZv;
#pragma unroll
        for (int k = 0; k < 4; k++) {
            cfX[k] = nfX[k]; cfY[k] = nfY[k]; cfZ[k] = nfZ[k];
            ri_cur[k] = ri_next[k];
        }
    }
}

// ---------------- fused kernel: rays (blocks 0..255) + transposed volP build ----------------
// Build block b handles (y = b/12, ztile = (b%12)*16): stage vol rows y,y+1
// for 16 z-planes in smem (coalesced reads), emit z-contiguous float4 runs
// (coalesced 256B half-warp writes).
__global__ void __launch_bounds__(128) ray_build_kernel(const float* __restrict__ RI,
                                                        const float* __restrict__ ray0,
                                                        const float* __restrict__ vol) {
    if (blockIdx.x < RAY_BLOCKS) {
        int warp_global = blockIdx.x * 4 + (threadIdx.x >> 5);
        ray_body(RI, ray0, warp_global, threadIdx.x & 31);
        return;
    }
    __shared__ float sm[ZTILE][2][OUTN];   // 16 z x 2 y x 192 x = 24KB

    int b  = blockIdx.x - RAY_BLOCKS;
    int y  = b / (OUTN / ZTILE);
    int z0 = (b % (OUTN / ZTILE)) * ZTILE;
    int y1 = min(y + 1, OUTN - 1);
    int tid = threadIdx.x;

    // Phase A: coalesced row reads
    for (int i = tid; i < ZTILE * 2 * OUTN; i += 128) {
        int zi   = i / (2 * OUTN);
        int rest = i % (2 * OUTN);
        int yi   = rest / OUTN;
        int x    = rest % OUTN;
        int yy   = yi ? y1 : y;
        sm[zi][yi][x] = __ldg(&vol[((z0 + zi) * OUTN + yy) * OUTN + x]);
    }
    __syncthreads();

    // Phase B: z-contiguous writes. lane pattern: zi = tid&15, x = base + tid>>4
    int zi = tid & (ZTILE - 1);
    int xo = tid >> 4;              // 0..7
    for (int xb = 0; xb < OUTN; xb += 8) {
        int x  = xb + xo;
        int x1 = min(x + 1, OUTN - 1);
        float4 v = make_float4(sm[zi][0][x], sm[zi][0][x1],
                               sm[zi][1][x], sm[zi][1][x1]);
        gVolP[((y * OUTN) + x) * OUTN + z0 + zi] = v;
    }
}

// ---------------- phase 2: lane t handles cc = q*32+t -> contiguous z addresses ----------------
__device__ __forceinline__ float4 load_plane_slow(int x0, int y0, int z) {
    bool zin  = ((unsigned)z        < 192u);
    bool x0in = ((unsigned)x0       < 192u);
    bool x1in = ((unsigned)(x0 + 1) < 192u);
    bool y0in = ((unsigned)y0       < 192u);
    bool y1in = ((unsigned)(y0 + 1) < 192u);
    int zc = min(max(z, 0), 191);
    int xs = min(max(x0, 0), 191);
    int ys = min(max(y0, 0), 191);
    float4 p = __ldg(&gVolP[((ys * OUTN) + xs) * OUTN + zc]);
    bool ax = (x0 >= 0), ay = (y0 >= 0);
    float t00 = p.x;
    float t01 = ax ? p.y : p.x;
    float t10 = ay ? p.z : p.x;
    float t11 = ax ? (ay ? p.w : p.y) : (ay ? p.z : p.x);
    float4 r;
    r.x = (zin && x0in && y0in) ? t00 : 0.0f;
    r.y = (zin && x1in && y0in) ? t01 : 0.0f;
    r.z = (zin && x0in && y1in) ? t10 : 0.0f;
    r.w = (zin && x1in && y1in) ? t11 : 0.0f;
    return r;
}

__global__ void __launch_bounds__(128) sample_kernel(float* __restrict__ out) {
    int w = threadIdx.x >> 5;
    int t = threadIdx.x & 31;
    int row = blockIdx.x * 4 + w;
    int aa = row / OUTN, bb = row % OUTN;

    __shared__ float4 G4[4][64];

    const float scale = 63.0f / 191.0f;
    float pa = (float)aa * scale; int i0 = min((int)pa, 62); float wi = pa - (float)i0;
    float pb = (float)bb * scale; int j0 = min((int)pb, 62); float wj = pb - (float)j0;
    float u = 1.0f - wi, v = 1.0f - wj;
    int base = (i0 << 12) + (j0 << 6);

#pragma unroll
    for (int sb = 0; sb < 2; sb++) {
        int s = t + sb * 32;
        float4 a00 = gM4[base + s],      a10 = gM4[base + 4096 + s];
        float4 a01 = gM4[base + 64 + s], a11 = gM4[base + 4160 + s];
        float4 g;
        g.x = (a00.x * u + a10.x * wi) * v + (a01.x * u + a11.x * wi) * wj;
        g.y = (a00.y * u + a10.y * wi) * v + (a01.y * u + a11.y * wi) * wj;
        g.z = (a00.z * u + a10.z * wi) * v + (a01.z * u + a11.z * wi) * wj;
        g.w = 0.0f;
        G4[w][s] = g;
    }
    __syncwarp();

    int obase = row * OUTN;
#pragma unroll
    for (int q = 0; q < 6; q++) {
        int cc = q * 32 + t;                 // consecutive cc across lanes
        float pc = (float)cc * scale; int s0 = min((int)pc, 62); float ws = pc - (float)s0;
        float4 g0 = G4[w][s0];
        float4 g1 = G4[w][s0 + 1];
        float gx = g0.x * (1.0f - ws) + g1.x * ws;
        float gy = g0.y * (1.0f - ws) + g1.y * ws;
        float gz = g0.z * (1.0f - ws) + g1.z * ws;

        float ix = (gx + 1.0f) * 0.5f * 191.0f;
        float iy = (gy + 1.0f) * 0.5f * 191.0f;
        float iz = (gz + 1.0f) * 0.5f * 191.0f;
        float xf = floorf(ix), yf = floorf(iy), zf = floorf(iz);
        float fx = ix - xf, fy = iy - yf, fz = iz - zf;
        int x0 = (int)xf, y0 = (int)yf, z0 = (int)zf;

        // z0 ~ cc across lanes: addresses contiguous (16B stride) in gVolP.
        float4 pl0, pl1;
        bool lane_ok = ((unsigned)x0 <= 190u) && ((unsigned)y0 <= 190u) &&
                       ((unsigned)z0 <= 190u);
        if (__all_sync(0xffffffffu, lane_ok)) {
            const float4* bp = &gVolP[((y0 * OUTN) + x0) * OUTN + z0];
            pl0 = __ldg(bp);
            pl1 = __ldg(bp + 1);
        } else {
            pl0 = load_plane_slow(x0, y0, z0);
            pl1 = load_plane_slow(x0, y0, z0 + 1);
        }

        float ux = 1.0f - fx, uy = 1.0f - fy;
        float r0 = uy * (ux * pl0.x + fx * pl0.y) + fy * (ux * pl0.z + fx * pl0.w);
        float r1 = uy * (ux * pl1.x + fx * pl1.y) + fy * (ux * pl1.z + fx * pl1.w);
        out[obase + cc] = r0 * (1.0f - fz) + r1 * fz;   // coalesced store
    }
}

// ---------------- launch ----------------
extern "C" void kernel_launch(void* const* d_in, const int* in_sizes, int n_in,
                              void* d_out, int out_size) {
    const float* phantom = nullptr;
    const float* RI      = nullptr;
    const float* ray0    = nullptr;
    for (int i = 0; i < n_in; i++) {
        if      (in_sizes[i] == OUT3)                phantom = (const float*)d_in[i];
        else if (in_sizes[i] == KGRID*KGRID*KGRID*2) RI      = (const float*)d_in[i];
        else if (in_sizes[i] == NRAY2 * 5)           ray0    = (const float*)d_in[i];
    }
    float* out = (float*)d_out;

    ray_build_kernel<<<RAY_BLOCKS + BUILD_BLOCKS, 128>>>(RI, ray0, phantom);
    sample_kernel<<<OUTN * OUTN / 4, 128>>>(out);
}

// round 11
// speedup vs baseline: 1.3266x; 1.3266x over previous
#include <cuda_runtime.h>
#include <math.h>

#define KGRID 64
#define NRAY2 4096
#define NS    64
#define OUTN  192
#define OUT3  (OUTN*OUTN*OUTN)

#define RAY_BLOCKS   128                       // 32 rays/block at 256 threads
#define BUILD_BLOCKS (OUTN * 6 * 6)            // y:192 x xtile:6 x ztile:6 = 6912

// ---------------- scratch ----------------
__device__ float4 gM4[NRAY2 * NS];   // mesh {2X-1, 2Y-1, 2z-1, _}
// z-FASTEST x-packed taps: gVolX2[(y*192 + x)*192 + z] = {v[z][y][x], v[z][y][x+1]}
// (x edge-replicated). 56MB -> stays L2-resident during sample.
__device__ float2 gVolX2[OUT3];

// ---------------- compile-time matrices ----------------
constexpr double c_sin(double x) {
    double x2 = x * x;
    return x * (1.0 + x2 * (-1.0/6.0 + x2 * (1.0/120.0 + x2 * (-1.0/5040.0
             + x2 * (1.0/362880.0 + x2 * (-1.0/39916800.0))))));
}
constexpr double c_cos(double x) {
    double x2 = x * x;
    return 1.0 + x2 * (-0.5 + x2 * (1.0/24.0 + x2 * (-1.0/720.0
             + x2 * (1.0/40320.0 + x2 * (-1.0/3628800.0 + x2 * (1.0/479001600.0))))));
}
struct M4m { double a[16]; };
constexpr M4m c_mul(const M4m& A, const M4m& B) {
    M4m C{};
    for (int i = 0; i < 4; i++)
        for (int j = 0; j < 4; j++) {
            double s = 0.0;
            for (int k = 0; k < 4; k++) s += A.a[i*4+k] * B.a[k*4+j];
            C.a[i*4+j] = s;
        }
    return C;
}
constexpr M4m c_ry(double t) { double c=c_cos(t), s=c_sin(t); return M4m{{1,0,0,0, 0,c,-s,0, 0,s,c,0, 0,0,0,1}}; }
constexpr M4m c_rx(double t) { double c=c_cos(t), s=c_sin(t); return M4m{{c,0,-s,0, 0,1,0,0, s,0,c,0, 0,0,0,1}}; }
constexpr M4m c_rz(double t) { double c=c_cos(t), s=c_sin(t); return M4m{{c,-s,0,0, s,c,0,0, 0,0,1,0, 0,0,0,1}}; }
struct Mats { float mc[12]; float md[12]; };
constexpr Mats build_mats() {
    const double TX = 0.1, TY = 0.05, TZ = 0.02, CX = 0.5;
    M4m RY  = c_ry(-TY), RY_ = c_ry( TY);
    M4m RX  = c_rx( TX), RX_ = c_rx(-TX);
    M4m RZ  = c_rz(-TZ), RZ_ = c_rz( TZ);
    M4m S1{{1,0,0,0, 0,1,0,0, 0,0,1,0, -CX,-CX,-CX,1}};
    M4m S2{{1,0,0,0, 0,1,0,0, 0,0,1,0,  CX, CX, CX,1}};
    M4m M_crd = c_mul(c_mul(c_mul(c_mul(S1, RZ), RY), RX), S2);
    M4m M_drv = c_mul(c_mul(RX_, RY_), RZ_);
    Mats r{};
    for (int i = 0; i < 4; i++)
        for (int j = 0; j < 3; j++) {
            r.mc[i*3+j] = (float)M_crd.a[i*4+j];
            r.md[i*3+j] = (float)M_drv.a[i*4+j];
        }
    return r;
}
__constant__ Mats cMat = build_mats();

// ---------------- ray-tracing body (R6 structure, proven) ----------------
__device__ __forceinline__ void ray_body(const float* __restrict__ RI,
                                         const float* __restrict__ ray0,
                                         int warp_global, int lane) {
    int grp  = (lane >> 3);
    int l    = lane & 7;
    int ray  = warp_global * 4 + grp;
    if (ray >= NRAY2) return;

    float mc[12], md[12];
#pragma unroll
    for (int i = 0; i < 12; i++) { mc[i] = cMat.mc[i]; md[i] = cMat.md[i]; }

    const float* r0 = ray0 + ray * 5;
    float X = r0[0], dX1 = r0[1], Y = r0[2], dY1 = r0[3], z = r0[4];

    float xr[4], yr[4], zr[4];
    bool  act[4];
#pragma unroll
    for (int k = 0; k < 4; k++) {
        int m = l + 8 * k;
        act[k] = (m < 27);
        int mm = act[k] ? m : 0;
        xr[k] = (float)((mm / 3) % 3 - 1);
        yr[k] = (float)(mm / 9 - 1);
        zr[k] = (float)(mm % 3 - 1);
    }

    const float2* ri2 = (const float2*)RI;
    const float STEP  = 1.0f / 63.0f;
    const float INV63 = 1.0f / 63.0f;

    if (l == 0)
        gM4[ray * NS] = make_float4(2.0f*X - 1.0f, 2.0f*Y - 1.0f, 2.0f*z - 1.0f, 0.0f);

    float cXv, cYv, cZv;
    float cfX[4], cfY[4], cfZ[4];
    float2 ri_cur[4];
    {
        float t0 = Y * mc[0] + X * mc[3] + z * mc[6] + mc[9];
        float t1 = Y * mc[1] + X * mc[4] + z * mc[7] + mc[10];
        float t2 = Y * mc[2] + X * mc[5] + z * mc[8] + mc[11];
        cXv = t1; cYv = t0; cZv = t2;
        float rX = rintf(cXv * 64.0f), rY = rintf(cYv * 64.0f), rZ = rintf(cZv * 64.0f);
#pragma unroll
        for (int k = 0; k < 4; k++) {
            cfX[k] = fminf(fmaxf(rX + xr[k], 0.0f), 63.0f);
            cfY[k] = fminf(fmaxf(rY + yr[k], 0.0f), 63.0f);
            cfZ[k] = fminf(fmaxf(rZ + zr[k], 0.0f), 63.0f);
            ri_cur[k] = make_float2(0.f, 1.f);
            if (act[k]) {
                int lin = ((int)cfY[k] << 12) + ((int)cfX[k] << 6) + (int)cfZ[k];
                ri_cur[k] = __ldg(&ri2[lin]);
            }
        }
    }

    for (int s = 1; s < NS; s++) {
        float Xn = X + dX1 * STEP;
        float Yn = Y + dY1 * STEP;
        float zn = z + STEP;

        float t0 = Yn * mc[0] + Xn * mc[3] + zn * mc[6] + mc[9];
        float t1 = Yn * mc[1] + Xn * mc[4] + zn * mc[7] + mc[10];
        float t2 = Yn * mc[2] + Xn * mc[5] + zn * mc[8] + mc[11];
        float nXv = t1, nYv = t0, nZv = t2;
        float rX = rintf(nXv * 64.0f), rY = rintf(nYv * 64.0f), rZ = rintf(nZv * 64.0f);
        float nfX[4], nfY[4], nfZ[4];
        float2 ri_next[4];
#pragma unroll
        for (int k = 0; k < 4; k++) {
            nfX[k] = fminf(fmaxf(rX + xr[k], 0.0f), 63.0f);
            nfY[k] = fminf(fmaxf(rY + yr[k], 0.0f), 63.0f);
            nfZ[k] = fminf(fmaxf(rZ + zr[k], 0.0f), 63.0f);
            ri_next[k] = make_float2(0.f, 1.f);
            if (act[k]) {
                int lin = ((int)nfY[k] << 12) + ((int)nfX[k] << 6) + (int)nfZ[k];
                ri_next[k] = __ldg(&ri2[lin]);
            }
        }

        float s_norm = 0.f, s_nus = 0.f, s_nx = 0.f, s_ny = 0.f,
              s_nz = 0.f, s_ndx = 0.f, s_ndy = 0.f, s_ndz = 0.f;
#pragma unroll
        for (int k = 0; k < 4; k++) {
            if (act[k]) {
                float dx  = cfX[k] * INV63 - cXv;
                float dy  = cfY[k] * INV63 - cYv;
                float dzv = cfZ[k] * INV63 - cZv;
                float A = ri_cur[k].x, sg = ri_cur[k].y;
                float inv_s2 = __fdividef(1.0f, sg * sg);
                float r2 = dx * dx + dy * dy + dzv * dzv;
                float ni = __expf(-r2 * 0.5f * inv_s2) + 2e-7f;
                float nu = ni * A;
                float hx = dx * inv_s2, hy = dy * inv_s2, hz = dzv * inv_s2;
                s_norm += ni;      s_nus += nu;
                s_nx += nu * hx;   s_ny += nu * hy;   s_nz += nu * hz;
                s_ndx += ni * hx;  s_ndy += ni * hy;  s_ndz += ni * hz;
            }
        }
#pragma unroll
        for (int off = 4; off > 0; off >>= 1) {
            s_norm += __shfl_xor_sync(0xffffffffu, s_norm, off);
            s_nus  += __shfl_xor_sync(0xffffffffu, s_nus,  off);
            s_nx   += __shfl_xor_sync(0xffffffffu, s_nx,   off);
            s_ny   += __shfl_xor_sync(0xffffffffu, s_ny,   off);
            s_nz   += __shfl_xor_sync(0xffffffffu, s_nz,   off);
            s_ndx  += __shfl_xor_sync(0xffffffffu, s_ndx,  off);
            s_ndy  += __shfl_xor_sync(0xffffffffu, s_ndy,  off);
            s_ndz  += __shfl_xor_sync(0xffffffffu, s_ndz,  off);
        }
        float inv_norm = __fdividef(1.0f, s_norm);
        float inv_n2 = inv_norm * inv_norm;
        float nx = (s_norm * s_nx - s_nus * s_ndx) * inv_n2;
        float ny = (s_norm * s_ny - s_nus * s_ndy) * inv_n2;
        float nz = (s_norm * s_nz - s_nus * s_ndz) * inv_n2;

        float d0 = ny * md[0] + nx * md[3] + nz * md[6] + md[9];
        float d1 = ny * md[1] + nx * md[4] + nz * md[7] + md[10];
        float d2 = ny * md[2] + nx * md[5] + nz * md[8] + md[11];
        float dndx = d1, dndz = d2, dndy = d0;

        float inv_n = __fdividef(s_norm, s_nus);
        float dX2 = (dndx - dndz * dX1) * (1.0f + dX1 * dX1) * inv_n;
        float dY2 = (dndy - dndz * dY1) * (1.0f + dY1 * dY1) * inv_n;

        dX1 += dX2 * STEP;
        dY1 += dY2 * STEP;
        X = Xn; Y = Yn; z = zn;

        if (l == 0)
            gM4[ray * NS + s] = make_float4(2.0f*X - 1.0f, 2.0f*Y - 1.0f, 2.0f*z - 1.0f, 0.0f);

        cXv = nXv; cYv = nYv; cZv = nZv;
#pragma unroll
        for (int k = 0; k < 4; k++) {
            cfX[k] = nfX[k]; cfY[k] = nfY[k]; cfZ[k] = nfZ[k];
            ri_cur[k] = ri_next[k];
        }
    }
}

// ---------------- fused kernel: rays (blocks 0..127) + x-pack transpose build ----------------
// Build block handles (y, 32 x, 32 z): stage 33 x-values for 32 z-planes in
// 4.3KB smem (coalesced x-row reads), emit z-contiguous float2 runs
// (256B/warp writes). 28MB read + 56MB write total, full occupancy.
__global__ void __launch_bounds__(256) ray_build_kernel(const float* __restrict__ RI,
                                                        const float* __restrict__ ray0,
                                                        const float* __restrict__ vol) {
    __shared__ float smA[32][34];     // [zi][xi], 33 used + pad

    if (blockIdx.x < RAY_BLOCKS) {
        int warp_global = blockIdx.x * 8 + (threadIdx.x >> 5);
        ray_body(RI, ray0, warp_global, threadIdx.x & 31);
        return;
    }
    int b  = blockIdx.x - RAY_BLOCKS;
    int y  = b / 36;
    int rest = b % 36;
    int x0 = (rest / 6) * 32;
    int z0 = (rest % 6) * 32;
    int tid = threadIdx.x;

    // Phase A: stage vol[z0+zi][y][x0 .. x0+32] (x clamped at 191)
    for (int i = tid; i < 32 * 33; i += 256) {
        int zi = i / 33;
        int xi = i % 33;
        int x  = min(x0 + xi, OUTN - 1);
        smA[zi][xi] = __ldg(&vol[((z0 + zi) * OUTN + y) * OUTN + x]);
    }
    __syncthreads();

    // Phase B: z-contiguous float2 writes; warp = 32 consecutive z at one x
    int zi = tid & 31;
    int xo = tid >> 5;                 // 0..7
#pragma unroll
    for (int xb = 0; xb < 32; xb += 8) {
        int xi = xb + xo;
        float2 v = make_float2(smA[zi][xi], smA[zi][xi + 1]);
        gVolX2[((y * OUTN) + x0 + xi) * OUTN + z0 + zi] = v;
    }
}

// ---------------- phase 2: lane t handles cc = q*32+t -> contiguous z addresses ----------------
// taps (x0, x0+1) at given (y, z), full OOB handling (boundary warps only)
__device__ __forceinline__ float2 tap2_slow(int x0, int y, int z) {
    bool zin  = ((unsigned)z        < 192u);
    bool yin  = ((unsigned)y        < 192u);
    bool x0in = ((unsigned)x0       < 192u);
    bool x1in = ((unsigned)(x0 + 1) < 192u);
    int zc = min(max(z, 0), 191);
    int yc = min(max(y, 0), 191);
    int xs = min(max(x0, 0), 191);
    float2 p = __ldg(&gVolX2[((yc * OUTN) + xs) * OUTN + zc]);
    bool ax = (x0 >= 0);
    float t0 = p.x;
    float t1 = ax ? p.y : p.x;
    float2 r;
    r.x = (zin && yin && x0in) ? t0 : 0.0f;
    r.y = (zin && yin && x1in) ? t1 : 0.0f;
    return r;
}

__global__ void __launch_bounds__(128) sample_kernel(float* __restrict__ out) {
    int w = threadIdx.x >> 5;
    int t = threadIdx.x & 31;
    int row = blockIdx.x * 4 + w;
    int aa = row / OUTN, bb = row % OUTN;

    __shared__ float4 G4[4][64];

    const float scale = 63.0f / 191.0f;
    float pa = (float)aa * scale; int i0 = min((int)pa, 62); float wi = pa - (float)i0;
    float pb = (float)bb * scale; int j0 = min((int)pb, 62); float wj = pb - (float)j0;
    float u = 1.0f - wi, v = 1.0f - wj;
    int base = (i0 << 12) + (j0 << 6);

#pragma unroll
    for (int sb = 0; sb < 2; sb++) {
        int s = t + sb * 32;
        float4 a00 = gM4[base + s],      a10 = gM4[base + 4096 + s];
        float4 a01 = gM4[base + 64 + s], a11 = gM4[base + 4160 + s];
        float4 g;
        g.x = (a00.x * u + a10.x * wi) * v + (a01.x * u + a11.x * wi) * wj;
        g.y = (a00.y * u + a10.y * wi) * v + (a01.y * u + a11.y * wi) * wj;
        g.z = (a00.z * u + a10.z * wi) * v + (a01.z * u + a11.z * wi) * wj;
        g.w = 0.0f;
        G4[w][s] = g;
    }
    __syncwarp();

    int obase = row * OUTN;
#pragma unroll
    for (int q = 0; q < 6; q++) {
        int cc = q * 32 + t;                 // consecutive cc across lanes
        float pc = (float)cc * scale; int s0 = min((int)pc, 62); float ws = pc - (float)s0;
        float4 g0 = G4[w][s0];
        float4 g1 = G4[w][s0 + 1];
        float gx = g0.x * (1.0f - ws) + g1.x * ws;
        float gy = g0.y * (1.0f - ws) + g1.y * ws;
        float gz = g0.z * (1.0f - ws) + g1.z * ws;

        float ix = (gx + 1.0f) * 0.5f * 191.0f;
        float iy = (gy + 1.0f) * 0.5f * 191.0f;
        float iz = (gz + 1.0f) * 0.5f * 191.0f;
        float xf = floorf(ix), yf = floorf(iy), zf = floorf(iz);
        float fx = ix - xf, fy = iy - yf, fz = iz - zf;
        int x0 = (int)xf, y0 = (int)yf, z0 = (int)zf;

        // z0 ~ cc across lanes: addresses contiguous (8B stride) in gVolX2.
        float2 a, bq, c, d;   // (y0,z0) (y0,z0+1) (y1,z0) (y1,z0+1)
        bool lane_ok = ((unsigned)x0 <= 190u) && ((unsigned)y0 <= 190u) &&
                       ((unsigned)z0 <= 190u);
        if (__all_sync(0xffffffffu, lane_ok)) {
            const float2* p0 = &gVolX2[((y0 * OUTN) + x0) * OUTN + z0];
            a  = __ldg(p0);
            bq = __ldg(p0 + 1);
            const float2* p1 = p0 + OUTN * OUTN;   // y0+1 row
            c  = __ldg(p1);
            d  = __ldg(p1 + 1);
        } else {
            a  = tap2_slow(x0, y0,     z0);
            bq = tap2_slow(x0, y0,     z0 + 1);
            c  = tap2_slow(x0, y0 + 1, z0);
            d  = tap2_slow(x0, y0 + 1, z0 + 1);
        }

        float ux = 1.0f - fx, uy = 1.0f - fy;
        float r0 = uy * (ux * a.x  + fx * a.y)  + fy * (ux * c.x + fx * c.y);
        float r1 = uy * (ux * bq.x + fx * bq.y) + fy * (ux * d.x + fx * d.y);
        out[obase + cc] = r0 * (1.0f - fz) + r1 * fz;   // coalesced store
    }
}

// ---------------- launch ----------------
extern "C" void kernel_launch(void* const* d_in, const int* in_sizes, int n_in,
                              void* d_out, int out_size) {
    const float* phantom = nullptr;
    const float* RI      = nullptr;
    const float* ray0    = nullptr;
    for (int i = 0; i < n_in; i++) {
        if      (in_sizes[i] == OUT3)                phantom = (const float*)d_in[i];
        else if (in_sizes[i] == KGRID*KGRID*KGRID*2) RI      = (const float*)d_in[i];
        else if (in_sizes[i] == NRAY2 * 5)           ray0    = (const float*)d_in[i];
    }
    float* out = (float*)d_out;

    ray_build_kernel<<<RAY_BLOCKS + BUILD_BLOCKS, 256>>>(RI, ray0, phantom);
    sample_kernel<<<OUTN * OUTN / 4, 128>>>(out);
}

// round 12
// speedup vs baseline: 1.5577x; 1.1742x over previous
#include <cuda_runtime.h>
#include <math.h>

#define KGRID 64
#define NRAY2 4096
#define NS    64
#define OUTN  192
#define OUT3  (OUTN*OUTN*OUTN)

#define FUSED_BLOCKS 256        // 256 blocks x 8 warps: w0-3 rays, w4-7 build
#define N_TILES      (OUTN * 6 * 6)   // y:192 x xtile:6 x ztile:6 = 6912
#define N_BUILD_WARPS (FUSED_BLOCKS * 4)

// ---------------- scratch ----------------
__device__ float4 gM4[NRAY2 * NS];   // mesh {2X-1, 2Y-1, 2z-1, _}
// z-FASTEST x-packed taps: gVolX2[(y*192 + x)*192 + z] = {v[z][y][x], v[z][y][x+1]}
__device__ float2 gVolX2[OUT3];

// ---------------- compile-time matrices ----------------
constexpr double c_sin(double x) {
    double x2 = x * x;
    return x * (1.0 + x2 * (-1.0/6.0 + x2 * (1.0/120.0 + x2 * (-1.0/5040.0
             + x2 * (1.0/362880.0 + x2 * (-1.0/39916800.0))))));
}
constexpr double c_cos(double x) {
    double x2 = x * x;
    return 1.0 + x2 * (-0.5 + x2 * (1.0/24.0 + x2 * (-1.0/720.0
             + x2 * (1.0/40320.0 + x2 * (-1.0/3628800.0 + x2 * (1.0/479001600.0))))));
}
struct M4m { double a[16]; };
constexpr M4m c_mul(const M4m& A, const M4m& B) {
    M4m C{};
    for (int i = 0; i < 4; i++)
        for (int j = 0; j < 4; j++) {
            double s = 0.0;
            for (int k = 0; k < 4; k++) s += A.a[i*4+k] * B.a[k*4+j];
            C.a[i*4+j] = s;
        }
    return C;
}
constexpr M4m c_ry(double t) { double c=c_cos(t), s=c_sin(t); return M4m{{1,0,0,0, 0,c,-s,0, 0,s,c,0, 0,0,0,1}}; }
constexpr M4m c_rx(double t) { double c=c_cos(t), s=c_sin(t); return M4m{{c,0,-s,0, 0,1,0,0, s,0,c,0, 0,0,0,1}}; }
constexpr M4m c_rz(double t) { double c=c_cos(t), s=c_sin(t); return M4m{{c,-s,0,0, s,c,0,0, 0,0,1,0, 0,0,0,1}}; }
struct Mats { float mc[12]; float md[12]; };
constexpr Mats build_mats() {
    const double TX = 0.1, TY = 0.05, TZ = 0.02, CX = 0.5;
    M4m RY  = c_ry(-TY), RY_ = c_ry( TY);
    M4m RX  = c_rx( TX), RX_ = c_rx(-TX);
    M4m RZ  = c_rz(-TZ), RZ_ = c_rz( TZ);
    M4m S1{{1,0,0,0, 0,1,0,0, 0,0,1,0, -CX,-CX,-CX,1}};
    M4m S2{{1,0,0,0, 0,1,0,0, 0,0,1,0,  CX, CX, CX,1}};
    M4m M_crd = c_mul(c_mul(c_mul(c_mul(S1, RZ), RY), RX), S2);
    M4m M_drv = c_mul(c_mul(RX_, RY_), RZ_);
    Mats r{};
    for (int i = 0; i < 4; i++)
        for (int j = 0; j < 3; j++) {
            r.mc[i*3+j] = (float)M_crd.a[i*4+j];
            r.md[i*3+j] = (float)M_drv.a[i*4+j];
        }
    return r;
}
__constant__ Mats cMat = build_mats();

// ---------------- ray-tracing body (R6 structure, proven) ----------------
__device__ __forceinline__ void ray_body(const float* __restrict__ RI,
                                         const float* __restrict__ ray0,
                                         int warp_global, int lane) {
    int grp  = (lane >> 3);
    int l    = lane & 7;
    int ray  = warp_global * 4 + grp;
    if (ray >= NRAY2) return;

    float mc[12], md[12];
#pragma unroll
    for (int i = 0; i < 12; i++) { mc[i] = cMat.mc[i]; md[i] = cMat.md[i]; }

    const float* r0 = ray0 + ray * 5;
    float X = r0[0], dX1 = r0[1], Y = r0[2], dY1 = r0[3], z = r0[4];

    float xr[4], yr[4], zr[4];
    bool  act[4];
#pragma unroll
    for (int k = 0; k < 4; k++) {
        int m = l + 8 * k;
        act[k] = (m < 27);
        int mm = act[k] ? m : 0;
        xr[k] = (float)((mm / 3) % 3 - 1);
        yr[k] = (float)(mm / 9 - 1);
        zr[k] = (float)(mm % 3 - 1);
    }

    const float2* ri2 = (const float2*)RI;
    const float STEP  = 1.0f / 63.0f;
    const float INV63 = 1.0f / 63.0f;

    if (l == 0)
        gM4[ray * NS] = make_float4(2.0f*X - 1.0f, 2.0f*Y - 1.0f, 2.0f*z - 1.0f, 0.0f);

    float cXv, cYv, cZv;
    float cfX[4], cfY[4], cfZ[4];
    float2 ri_cur[4];
    {
        float t0 = Y * mc[0] + X * mc[3] + z * mc[6] + mc[9];
        float t1 = Y * mc[1] + X * mc[4] + z * mc[7] + mc[10];
        float t2 = Y * mc[2] + X * mc[5] + z * mc[8] + mc[11];
        cXv = t1; cYv = t0; cZv = t2;
        float rX = rintf(cXv * 64.0f), rY = rintf(cYv * 64.0f), rZ = rintf(cZv * 64.0f);
#pragma unroll
        for (int k = 0; k < 4; k++) {
            cfX[k] = fminf(fmaxf(rX + xr[k], 0.0f), 63.0f);
            cfY[k] = fminf(fmaxf(rY + yr[k], 0.0f), 63.0f);
            cfZ[k] = fminf(fmaxf(rZ + zr[k], 0.0f), 63.0f);
            ri_cur[k] = make_float2(0.f, 1.f);
            if (act[k]) {
                int lin = ((int)cfY[k] << 12) + ((int)cfX[k] << 6) + (int)cfZ[k];
                ri_cur[k] = __ldg(&ri2[lin]);
            }
        }
    }

    for (int s = 1; s < NS; s++) {
        float Xn = X + dX1 * STEP;
        float Yn = Y + dY1 * STEP;
        float zn = z + STEP;

        float t0 = Yn * mc[0] + Xn * mc[3] + zn * mc[6] + mc[9];
        float t1 = Yn * mc[1] + Xn * mc[4] + zn * mc[7] + mc[10];
        float t2 = Yn * mc[2] + Xn * mc[5] + zn * mc[8] + mc[11];
        float nXv = t1, nYv = t0, nZv = t2;
        float rX = rintf(nXv * 64.0f), rY = rintf(nYv * 64.0f), rZ = rintf(nZv * 64.0f);
        float nfX[4], nfY[4], nfZ[4];
        float2 ri_next[4];
#pragma unroll
        for (int k = 0; k < 4; k++) {
            nfX[k] = fminf(fmaxf(rX + xr[k], 0.0f), 63.0f);
            nfY[k] = fminf(fmaxf(rY + yr[k], 0.0f), 63.0f);
            nfZ[k] = fminf(fmaxf(rZ + zr[k], 0.0f), 63.0f);
            ri_next[k] = make_float2(0.f, 1.f);
            if (act[k]) {
                int lin = ((int)nfY[k] << 12) + ((int)nfX[k] << 6) + (int)nfZ[k];
                ri_next[k] = __ldg(&ri2[lin]);
            }
        }

        float s_norm = 0.f, s_nus = 0.f, s_nx = 0.f, s_ny = 0.f,
              s_nz = 0.f, s_ndx = 0.f, s_ndy = 0.f, s_ndz = 0.f;
#pragma unroll
        for (int k = 0; k < 4; k++) {
            if (act[k]) {
                float dx  = cfX[k] * INV63 - cXv;
                float dy  = cfY[k] * INV63 - cYv;
                float dzv = cfZ[k] * INV63 - cZv;
                float A = ri_cur[k].x, sg = ri_cur[k].y;
                float inv_s2 = __fdividef(1.0f, sg * sg);
                float r2 = dx * dx + dy * dy + dzv * dzv;
                float ni = __expf(-r2 * 0.5f * inv_s2) + 2e-7f;
                float nu = ni * A;
                float hx = dx * inv_s2, hy = dy * inv_s2, hz = dzv * inv_s2;
                s_norm += ni;      s_nus += nu;
                s_nx += nu * hx;   s_ny += nu * hy;   s_nz += nu * hz;
                s_ndx += ni * hx;  s_ndy += ni * hy;  s_ndz += ni * hz;
            }
        }
#pragma unroll
        for (int off = 4; off > 0; off >>= 1) {
            s_norm += __shfl_xor_sync(0xffffffffu, s_norm, off);
            s_nus  += __shfl_xor_sync(0xffffffffu, s_nus,  off);
            s_nx   += __shfl_xor_sync(0xffffffffu, s_nx,   off);
            s_ny   += __shfl_xor_sync(0xffffffffu, s_ny,   off);
            s_nz   += __shfl_xor_sync(0xffffffffu, s_nz,   off);
            s_ndx  += __shfl_xor_sync(0xffffffffu, s_ndx,  off);
            s_ndy  += __shfl_xor_sync(0xffffffffu, s_ndy,  off);
            s_ndz  += __shfl_xor_sync(0xffffffffu, s_ndz,  off);
        }
        float inv_norm = __fdividef(1.0f, s_norm);
        float inv_n2 = inv_norm * inv_norm;
        float nx = (s_norm * s_nx - s_nus * s_ndx) * inv_n2;
        float ny = (s_norm * s_ny - s_nus * s_ndy) * inv_n2;
        float nz = (s_norm * s_nz - s_nus * s_ndz) * inv_n2;

        float d0 = ny * md[0] + nx * md[3] + nz * md[6] + md[9];
        float d1 = ny * md[1] + nx * md[4] + nz * md[7] + md[10];
        float d2 = ny * md[2] + nx * md[5] + nz * md[8] + md[11];
        float dndx = d1, dndz = d2, dndy = d0;

        float inv_n = __fdividef(s_norm, s_nus);
        float dX2 = (dndx - dndz * dX1) * (1.0f + dX1 * dX1) * inv_n;
        float dY2 = (dndy - dndz * dY1) * (1.0f + dY1 * dY1) * inv_n;

        dX1 += dX2 * STEP;
        dY1 += dY2 * STEP;
        X = Xn; Y = Yn; z = zn;

        if (l == 0)
            gM4[ray * NS + s] = make_float4(2.0f*X - 1.0f, 2.0f*Y - 1.0f, 2.0f*z - 1.0f, 0.0f);

        cXv = nXv; cYv = nYv; cZv = nZv;
#pragma unroll
        for (int k = 0; k < 4; k++) {
            cfX[k] = nfX[k]; cfY[k] = nfY[k]; cfZ[k] = nfZ[k];
            ri_cur[k] = ri_next[k];
        }
    }
}

// ---------------- per-warp transpose tile: (y, 32x, 32z), warp-private smem ----------------
// Phase A: 32 coalesced row reads into smA[zi][lane] (+ lane31 loads xi=32).
// Phase B: 32 z-contiguous 256B float2 stores (smA[lane][xi] reads are
// conflict-free: stride 33 words -> bank = (lane+xi)%32, distinct per lane).
__device__ __forceinline__ void build_tile(float (*smA)[33],
                                           const float* __restrict__ vol,
                                           int tile, int lane) {
    int y    = tile / 36;
    int rest = tile % 36;
    int x0   = (rest / 6) * 32;
    int z0   = (rest % 6) * 32;
    int xlast = min(x0 + 32, OUTN - 1);

#pragma unroll 4
    for (int zi = 0; zi < 32; zi++) {
        const float* rowp = &vol[((z0 + zi) * OUTN + y) * OUTN];
        smA[zi][lane] = __ldg(rowp + x0 + lane);
        if (lane == 31) smA[zi][32] = __ldg(rowp + xlast);
    }
    __syncwarp();

#pragma unroll 4
    for (int xi = 0; xi < 32; xi++) {
        float2 v = make_float2(smA[lane][xi], smA[lane][xi + 1]);
        gVolX2[((y * OUTN) + x0 + xi) * OUTN + z0 + lane] = v;
    }
    __syncwarp();
}

// ---------------- fused kernel: warps 0-3 rays, warps 4-7 transpose build ----------------
__global__ void __launch_bounds__(256) ray_build_kernel(const float* __restrict__ RI,
                                                        const float* __restrict__ ray0,
                                                        const float* __restrict__ vol) {
    __shared__ float smA[4][32][33];    // one 4.2KB slice per build warp

    int wid  = threadIdx.x >> 5;
    int lane = threadIdx.x & 31;

    if (wid < 4) {
        int warp_global = blockIdx.x * 4 + wid;     // 0..1023
        ray_body(RI, ray0, warp_global, lane);
    } else {
        int bw = blockIdx.x * 4 + (wid - 4);        // 0..1023 build warp id
        for (int tile = bw; tile < N_TILES; tile += N_BUILD_WARPS)
            build_tile(smA[wid - 4], vol, tile, lane);
    }
}

// ---------------- phase 2: lane t handles cc = q*32+t -> contiguous z addresses ----------------
__device__ __forceinline__ float2 tap2_slow(int x0, int y, int z) {
    bool zin  = ((unsigned)z        < 192u);
    bool yin  = ((unsigned)y        < 192u);
    bool x0in = ((unsigned)x0       < 192u);
    bool x1in = ((unsigned)(x0 + 1) < 192u);
    int zc = min(max(z, 0), 191);
    int yc = min(max(y, 0), 191);
    int xs = min(max(x0, 0), 191);
    float2 p = __ldg(&gVolX2[((yc * OUTN) + xs) * OUTN + zc]);
    bool ax = (x0 >= 0);
    float t0 = p.x;
    float t1 = ax ? p.y : p.x;
    float2 r;
    r.x = (zin && yin && x0in) ? t0 : 0.0f;
    r.y = (zin && yin && x1in) ? t1 : 0.0f;
    return r;
}

__global__ void __launch_bounds__(128) sample_kernel(float* __restrict__ out) {
    int w = threadIdx.x >> 5;
    int t = threadIdx.x & 31;
    int row = blockIdx.x * 4 + w;
    int aa = row / OUTN, bb = row % OUTN;

    __shared__ float4 G4[4][64];

    const float scale = 63.0f / 191.0f;
    float pa = (float)aa * scale; int i0 = min((int)pa, 62); float wi = pa - (float)i0;
    float pb = (float)bb * scale; int j0 = min((int)pb, 62); float wj = pb - (float)j0;
    float u = 1.0f - wi, v = 1.0f - wj;
    int base = (i0 << 12) + (j0 << 6);

#pragma unroll
    for (int sb = 0; sb < 2; sb++) {
        int s = t + sb * 32;
        float4 a00 = gM4[base + s],      a10 = gM4[base + 4096 + s];
        float4 a01 = gM4[base + 64 + s], a11 = gM4[base + 4160 + s];
        float4 g;
        g.x = (a00.x * u + a10.x * wi) * v + (a01.x * u + a11.x * wi) * wj;
        g.y = (a00.y * u + a10.y * wi) * v + (a01.y * u + a11.y * wi) * wj;
        g.z = (a00.z * u + a10.z * wi) * v + (a01.z * u + a11.z * wi) * wj;
        g.w = 0.0f;
        G4[w][s] = g;
    }
    __syncwarp();

    int obase = row * OUTN;
#pragma unroll
    for (int q = 0; q < 6; q++) {
        int cc = q * 32 + t;
        float pc = (float)cc * scale; int s0 = min((int)pc, 62); float ws = pc - (float)s0;
        float4 g0 = G4[w][s0];
        float4 g1 = G4[w][s0 + 1];
        float gx = g0.x * (1.0f - ws) + g1.x * ws;
        float gy = g0.y * (1.0f - ws) + g1.y * ws;
        float gz = g0.z * (1.0f - ws) + g1.z * ws;

        float ix = (gx + 1.0f) * 0.5f * 191.0f;
        float iy = (gy + 1.0f) * 0.5f * 191.0f;
        float iz = (gz + 1.0f) * 0.5f * 191.0f;
        float xf = floorf(ix), yf = floorf(iy), zf = floorf(iz);
        float fx = ix - xf, fy = iy - yf, fz = iz - zf;
        int x0 = (int)xf, y0 = (int)yf, z0 = (int)zf;

        float2 a, bq, c, d;   // (y0,z0) (y0,z0+1) (y1,z0) (y1,z0+1)
        bool lane_ok = ((unsigned)x0 <= 190u) && ((unsigned)y0 <= 190u) &&
                       ((unsigned)z0 <= 190u);
        if (__all_sync(0xffffffffu, lane_ok)) {
            const float2* p0 = &gVolX2[((y0 * OUTN) + x0) * OUTN + z0];
            a  = __ldg(p0);
            bq = __ldg(p0 + 1);
            const float2* p1 = p0 + OUTN * OUTN;
            c  = __ldg(p1);
            d  = __ldg(p1 + 1);
        } else {
            a  = tap2_slow(x0, y0,     z0);
            bq = tap2_slow(x0, y0,     z0 + 1);
            c  = tap2_slow(x0, y0 + 1, z0);
            d  = tap2_slow(x0, y0 + 1, z0 + 1);
        }

        float ux = 1.0f - fx, uy = 1.0f - fy;
        float r0 = uy * (ux * a.x  + fx * a.y)  + fy * (ux * c.x + fx * c.y);
        float r1 = uy * (ux * bq.x + fx * bq.y) + fy * (ux * d.x + fx * d.y);
        out[obase + cc] = r0 * (1.0f - fz) + r1 * fz;
    }
}

// ---------------- launch ----------------
extern "C" void kernel_launch(void* const* d_in, const int* in_sizes, int n_in,
                              void* d_out, int out_size) {
    const float* phantom = nullptr;
    const float* RI      = nullptr;
    const float* ray0    = nullptr;
    for (int i = 0; i < n_in; i++) {
        if      (in_sizes[i] == OUT3)                phantom = (const float*)d_in[i];
        else if (in_sizes[i] == KGRID*KGRID*KGRID*2) RI      = (const float*)d_in[i];
        else if (in_sizes[i] == NRAY2 * 5)           ray0    = (const float*)d_in[i];
    }
    float* out = (float*)d_out;

    ray_build_kernel<<<FUSED_BLOCKS, 256>>>(RI, ray0, phantom);
    sample_kernel<<<OUTN * OUTN / 4, 128>>>(out);
}

// round 13
// speedup vs baseline: 1.5670x; 1.0060x over previous
#include <cuda_runtime.h>
#include <math.h>

#define KGRID 64
#define NRAY2 4096
#define NS    64
#define OUTN  192
#define OUT3  (OUTN*OUTN*OUTN)

#define FUSED_BLOCKS 148        // exactly 1 block/SM: 7 ray warps + 9 build warps
#define RAY_WARPS_PER_BLOCK 7
#define BUILD_WARPS_PER_BLOCK 9
#define N_TILES      (OUTN * 6 * 6)   // 6912
#define N_BUILD_WARPS (FUSED_BLOCKS * BUILD_WARPS_PER_BLOCK)   // 1332

// ---------------- scratch ----------------
__device__ float4 gM4[NRAY2 * NS];   // mesh {2X-1, 2Y-1, 2z-1, _}
// z-FASTEST x-packed taps: gVolX2[(y*192 + x)*192 + z] = {v[z][y][x], v[z][y][x+1]}
__device__ float2 gVolX2[OUT3];

// ---------------- compile-time matrices ----------------
constexpr double c_sin(double x) {
    double x2 = x * x;
    return x * (1.0 + x2 * (-1.0/6.0 + x2 * (1.0/120.0 + x2 * (-1.0/5040.0
             + x2 * (1.0/362880.0 + x2 * (-1.0/39916800.0))))));
}
constexpr double c_cos(double x) {
    double x2 = x * x;
    return 1.0 + x2 * (-0.5 + x2 * (1.0/24.0 + x2 * (-1.0/720.0
             + x2 * (1.0/40320.0 + x2 * (-1.0/3628800.0 + x2 * (1.0/479001600.0))))));
}
struct M4m { double a[16]; };
constexpr M4m c_mul(const M4m& A, const M4m& B) {
    M4m C{};
    for (int i = 0; i < 4; i++)
        for (int j = 0; j < 4; j++) {
            double s = 0.0;
            for (int k = 0; k < 4; k++) s += A.a[i*4+k] * B.a[k*4+j];
            C.a[i*4+j] = s;
        }
    return C;
}
constexpr M4m c_ry(double t) { double c=c_cos(t), s=c_sin(t); return M4m{{1,0,0,0, 0,c,-s,0, 0,s,c,0, 0,0,0,1}}; }
constexpr M4m c_rx(double t) { double c=c_cos(t), s=c_sin(t); return M4m{{c,0,-s,0, 0,1,0,0, s,0,c,0, 0,0,0,1}}; }
constexpr M4m c_rz(double t) { double c=c_cos(t), s=c_sin(t); return M4m{{c,-s,0,0, s,c,0,0, 0,0,1,0, 0,0,0,1}}; }
struct Mats { float mc[12]; float md[12]; };
constexpr Mats build_mats() {
    const double TX = 0.1, TY = 0.05, TZ = 0.02, CX = 0.5;
    M4m RY  = c_ry(-TY), RY_ = c_ry( TY);
    M4m RX  = c_rx( TX), RX_ = c_rx(-TX);
    M4m RZ  = c_rz(-TZ), RZ_ = c_rz( TZ);
    M4m S1{{1,0,0,0, 0,1,0,0, 0,0,1,0, -CX,-CX,-CX,1}};
    M4m S2{{1,0,0,0, 0,1,0,0, 0,0,1,0,  CX, CX, CX,1}};
    M4m M_crd = c_mul(c_mul(c_mul(c_mul(S1, RZ), RY), RX), S2);
    M4m M_drv = c_mul(c_mul(RX_, RY_), RZ_);
    Mats r{};
    for (int i = 0; i < 4; i++)
        for (int j = 0; j < 3; j++) {
            r.mc[i*3+j] = (float)M_crd.a[i*4+j];
            r.md[i*3+j] = (float)M_drv.a[i*4+j];
        }
    return r;
}
__constant__ Mats cMat = build_mats();

// ---------------- ray-tracing body (R6 structure, proven) ----------------
__device__ __forceinline__ void ray_body(const float* __restrict__ RI,
                                         const float* __restrict__ ray0,
                                         int warp_global, int lane) {
    int grp  = (lane >> 3);
    int l    = lane & 7;
    int ray  = warp_global * 4 + grp;
    if (ray >= NRAY2) return;

    float mc[12], md[12];
#pragma unroll
    for (int i = 0; i < 12; i++) { mc[i] = cMat.mc[i]; md[i] = cMat.md[i]; }

    const float* r0 = ray0 + ray * 5;
    float X = r0[0], dX1 = r0[1], Y = r0[2], dY1 = r0[3], z = r0[4];

    float xr[4], yr[4], zr[4];
    bool  act[4];
#pragma unroll
    for (int k = 0; k < 4; k++) {
        int m = l + 8 * k;
        act[k] = (m < 27);
        int mm = act[k] ? m : 0;
        xr[k] = (float)((mm / 3) % 3 - 1);
        yr[k] = (float)(mm / 9 - 1);
        zr[k] = (float)(mm % 3 - 1);
    }

    const float2* ri2 = (const float2*)RI;
    const float STEP  = 1.0f / 63.0f;
    const float INV63 = 1.0f / 63.0f;

    if (l == 0)
        gM4[ray * NS] = make_float4(2.0f*X - 1.0f, 2.0f*Y - 1.0f, 2.0f*z - 1.0f, 0.0f);

    float cXv, cYv, cZv;
    float cfX[4], cfY[4], cfZ[4];
    float2 ri_cur[4];
    {
        float t0 = Y * mc[0] + X * mc[3] + z * mc[6] + mc[9];
        float t1 = Y * mc[1] + X * mc[4] + z * mc[7] + mc[10];
        float t2 = Y * mc[2] + X * mc[5] + z * mc[8] + mc[11];
        cXv = t1; cYv = t0; cZv = t2;
        float rX = rintf(cXv * 64.0f), rY = rintf(cYv * 64.0f), rZ = rintf(cZv * 64.0f);
#pragma unroll
        for (int k = 0; k < 4; k++) {
            cfX[k] = fminf(fmaxf(rX + xr[k], 0.0f), 63.0f);
            cfY[k] = fminf(fmaxf(rY + yr[k], 0.0f), 63.0f);
            cfZ[k] = fminf(fmaxf(rZ + zr[k], 0.0f), 63.0f);
            ri_cur[k] = make_float2(0.f, 1.f);
            if (act[k]) {
                int lin = ((int)cfY[k] << 12) + ((int)cfX[k] << 6) + (int)cfZ[k];
                ri_cur[k] = __ldg(&ri2[lin]);
            }
        }
    }

    for (int s = 1; s < NS; s++) {
        float Xn = X + dX1 * STEP;
        float Yn = Y + dY1 * STEP;
        float zn = z + STEP;

        float t0 = Yn * mc[0] + Xn * mc[3] + zn * mc[6] + mc[9];
        float t1 = Yn * mc[1] + Xn * mc[4] + zn * mc[7] + mc[10];
        float t2 = Yn * mc[2] + Xn * mc[5] + zn * mc[8] + mc[11];
        float nXv = t1, nYv = t0, nZv = t2;
        float rX = rintf(nXv * 64.0f), rY = rintf(nYv * 64.0f), rZ = rintf(nZv * 64.0f);
        float nfX[4], nfY[4], nfZ[4];
        float2 ri_next[4];
#pragma unroll
        for (int k = 0; k < 4; k++) {
            nfX[k] = fminf(fmaxf(rX + xr[k], 0.0f), 63.0f);
            nfY[k] = fminf(fmaxf(rY + yr[k], 0.0f), 63.0f);
            nfZ[k] = fminf(fmaxf(rZ + zr[k], 0.0f), 63.0f);
            ri_next[k] = make_float2(0.f, 1.f);
            if (act[k]) {
                int lin = ((int)nfY[k] << 12) + ((int)nfX[k] << 6) + (int)nfZ[k];
                ri_next[k] = __ldg(&ri2[lin]);
            }
        }

        float s_norm = 0.f, s_nus = 0.f, s_nx = 0.f, s_ny = 0.f,
              s_nz = 0.f, s_ndx = 0.f, s_ndy = 0.f, s_ndz = 0.f;
#pragma unroll
        for (int k = 0; k < 4; k++) {
            if (act[k]) {
                float dx  = cfX[k] * INV63 - cXv;
                float dy  = cfY[k] * INV63 - cYv;
                float dzv = cfZ[k] * INV63 - cZv;
                float A = ri_cur[k].x, sg = ri_cur[k].y;
                float inv_s2 = __fdividef(1.0f, sg * sg);
                float r2 = dx * dx + dy * dy + dzv * dzv;
                float ni = __expf(-r2 * 0.5f * inv_s2) + 2e-7f;
                float nu = ni * A;
                float hx = dx * inv_s2, hy = dy * inv_s2, hz = dzv * inv_s2;
                s_norm += ni;      s_nus += nu;
                s_nx += nu * hx;   s_ny += nu * hy;   s_nz += nu * hz;
                s_ndx += ni * hx;  s_ndy += ni * hy;  s_ndz += ni * hz;
            }
        }
#pragma unroll
        for (int off = 4; off > 0; off >>= 1) {
            s_norm += __shfl_xor_sync(0xffffffffu, s_norm, off);
            s_nus  += __shfl_xor_sync(0xffffffffu, s_nus,  off);
            s_nx   += __shfl_xor_sync(0xffffffffu, s_nx,   off);
            s_ny   += __shfl_xor_sync(0xffffffffu, s_ny,   off);
            s_nz   += __shfl_xor_sync(0xffffffffu, s_nz,   off);
            s_ndx  += __shfl_xor_sync(0xffffffffu, s_ndx,  off);
            s_ndy  += __shfl_xor_sync(0xffffffffu, s_ndy,  off);
            s_ndz  += __shfl_xor_sync(0xffffffffu, s_ndz,  off);
        }
        float inv_norm = __fdividef(1.0f, s_norm);
        float inv_n2 = inv_norm * inv_norm;
        float nx = (s_norm * s_nx - s_nus * s_ndx) * inv_n2;
        float ny = (s_norm * s_ny - s_nus * s_ndy) * inv_n2;
        float nz = (s_norm * s_nz - s_nus * s_ndz) * inv_n2;

        float d0 = ny * md[0] + nx * md[3] + nz * md[6] + md[9];
        float d1 = ny * md[1] + nx * md[4] + nz * md[7] + md[10];
        float d2 = ny * md[2] + nx * md[5] + nz * md[8] + md[11];
        float dndx = d1, dndz = d2, dndy = d0;

        float inv_n = __fdividef(s_norm, s_nus);
        float dX2 = (dndx - dndz * dX1) * (1.0f + dX1 * dX1) * inv_n;
        float dY2 = (dndy - dndz * dY1) * (1.0f + dY1 * dY1) * inv_n;

        dX1 += dX2 * STEP;
        dY1 += dY2 * STEP;
        X = Xn; Y = Yn; z = zn;

        if (l == 0)
            gM4[ray * NS + s] = make_float4(2.0f*X - 1.0f, 2.0f*Y - 1.0f, 2.0f*z - 1.0f, 0.0f);

        cXv = nXv; cYv = nYv; cZv = nZv;
#pragma unroll
        for (int k = 0; k < 4; k++) {
            cfX[k] = nfX[k]; cfY[k] = nfY[k]; cfZ[k] = nfZ[k];
            ri_cur[k] = ri_next[k];
        }
    }
}

// ---------------- per-warp transpose tile: (y, 32x, 32z), warp-private smem ----------------
__device__ __forceinline__ void build_tile(float (*smA)[33],
                                           const float* __restrict__ vol,
                                           int tile, int lane) {
    int y    = tile / 36;
    int rest = tile % 36;
    int x0   = (rest / 6) * 32;
    int z0   = (rest % 6) * 32;
    int xlast = min(x0 + 32, OUTN - 1);

#pragma unroll 4
    for (int zi = 0; zi < 32; zi++) {
        const float* rowp = &vol[((z0 + zi) * OUTN + y) * OUTN];
        smA[zi][lane] = __ldg(rowp + x0 + lane);
        if (lane == 31) smA[zi][32] = __ldg(rowp + xlast);
    }
    __syncwarp();

#pragma unroll 4
    for (int xi = 0; xi < 32; xi++) {
        float2 v = make_float2(smA[lane][xi], smA[lane][xi + 1]);
        gVolX2[((y * OUTN) + x0 + xi) * OUTN + z0 + lane] = v;
    }
    __syncwarp();
}

// ---------------- fused kernel: 1 block/SM, warps 0-6 rays, 7-15 build ----------------
__global__ void __launch_bounds__(512) ray_build_kernel(const float* __restrict__ RI,
                                                        const float* __restrict__ ray0,
                                                        const float* __restrict__ vol) {
    __shared__ float smA[BUILD_WARPS_PER_BLOCK][32][33];   // 38KB

    int wid  = threadIdx.x >> 5;
    int lane = threadIdx.x & 31;

    if (wid < RAY_WARPS_PER_BLOCK) {
        int warp_global = blockIdx.x * RAY_WARPS_PER_BLOCK + wid;   // 0..1035
        if (warp_global < NRAY2 / 4)
            ray_body(RI, ray0, warp_global, lane);
    } else {
        int bw = blockIdx.x * BUILD_WARPS_PER_BLOCK + (wid - RAY_WARPS_PER_BLOCK);
        for (int tile = bw; tile < N_TILES; tile += N_BUILD_WARPS)
            build_tile(smA[wid - RAY_WARPS_PER_BLOCK], vol, tile, lane);
    }
}

// ---------------- phase 2: lane t handles cc = q*32+t -> contiguous z addresses ----------------
__device__ __forceinline__ float2 tap2_slow(int x0, int y, int z) {
    bool zin  = ((unsigned)z        < 192u);
    bool yin  = ((unsigned)y        < 192u);
    bool x0in = ((unsigned)x0       < 192u);
    bool x1in = ((unsigned)(x0 + 1) < 192u);
    int zc = min(max(z, 0), 191);
    int yc = min(max(y, 0), 191);
    int xs = min(max(x0, 0), 191);
    float2 p = __ldg(&gVolX2[((yc * OUTN) + xs) * OUTN + zc]);
    bool ax = (x0 >= 0);
    float t0 = p.x;
    float t1 = ax ? p.y : p.x;
    float2 r;
    r.x = (zin && yin && x0in) ? t0 : 0.0f;
    r.y = (zin && yin && x1in) ? t1 : 0.0f;
    return r;
}

__global__ void __launch_bounds__(256) sample_kernel(float* __restrict__ out) {
    int w = threadIdx.x >> 5;
    int t = threadIdx.x & 31;
    int row = blockIdx.x * 8 + w;
    int aa = row / OUTN, bb = row % OUTN;

    __shared__ float4 G4[8][64];

    const float scale = 63.0f / 191.0f;
    float pa = (float)aa * scale; int i0 = min((int)pa, 62); float wi = pa - (float)i0;
    float pb = (float)bb * scale; int j0 = min((int)pb, 62); float wj = pb - (float)j0;
    float u = 1.0f - wi, v = 1.0f - wj;
    int base = (i0 << 12) + (j0 << 6);

#pragma unroll
    for (int sb = 0; sb < 2; sb++) {
        int s = t + sb * 32;
        float4 a00 = gM4[base + s],      a10 = gM4[base + 4096 + s];
        float4 a01 = gM4[base + 64 + s], a11 = gM4[base + 4160 + s];
        float4 g;
        g.x = (a00.x * u + a10.x * wi) * v + (a01.x * u + a11.x * wi) * wj;
        g.y = (a00.y * u + a10.y * wi) * v + (a01.y * u + a11.y * wi) * wj;
        g.z = (a00.z * u + a10.z * wi) * v + (a01.z * u + a11.z * wi) * wj;
        g.w = 0.0f;
        G4[w][s] = g;
    }
    __syncwarp();

    int obase = row * OUTN;
#pragma unroll
    for (int q = 0; q < 6; q++) {
        int cc = q * 32 + t;
        float pc = (float)cc * scale; int s0 = min((int)pc, 62); float ws = pc - (float)s0;
        float4 g0 = G4[w][s0];
        float4 g1 = G4[w][s0 + 1];
        float gx = g0.x * (1.0f - ws) + g1.x * ws;
        float gy = g0.y * (1.0f - ws) + g1.y * ws;
        float gz = g0.z * (1.0f - ws) + g1.z * ws;

        float ix = (gx + 1.0f) * 0.5f * 191.0f;
        float iy = (gy + 1.0f) * 0.5f * 191.0f;
        float iz = (gz + 1.0f) * 0.5f * 191.0f;
        float xf = floorf(ix), yf = floorf(iy), zf = floorf(iz);
        float fx = ix - xf, fy = iy - yf, fz = iz - zf;
        int x0 = (int)xf, y0 = (int)yf, z0 = (int)zf;

        float2 a, bq, c, d;   // (y0,z0) (y0,z0+1) (y1,z0) (y1,z0+1)
        bool lane_ok = ((unsigned)x0 <= 190u) && ((unsigned)y0 <= 190u) &&
                       ((unsigned)z0 <= 190u);
        if (__all_sync(0xffffffffu, lane_ok)) {
            const float2* p0 = &gVolX2[((y0 * OUTN) + x0) * OUTN + z0];
            a  = __ldg(p0);
            bq = __ldg(p0 + 1);
            const float2* p1 = p0 + OUTN * OUTN;
            c  = __ldg(p1);
            d  = __ldg(p1 + 1);
        } else {
            a  = tap2_slow(x0, y0,     z0);
            bq = tap2_slow(x0, y0,     z0 + 1);
            c  = tap2_slow(x0, y0 + 1, z0);
            d  = tap2_slow(x0, y0 + 1, z0 + 1);
        }

        float ux = 1.0f - fx, uy = 1.0f - fy;
        float r0 = uy * (ux * a.x  + fx * a.y)  + fy * (ux * c.x + fx * c.y);
        float r1 = uy * (ux * bq.x + fx * bq.y) + fy * (ux * d.x + fx * d.y);
        out[obase + cc] = r0 * (1.0f - fz) + r1 * fz;
    }
}

// ---------------- launch ----------------
extern "C" void kernel_launch(void* const* d_in, const int* in_sizes, int n_in,
                              void* d_out, int out_size) {
    const float* phantom = nullptr;
    const float* RI      = nullptr;
    const float* ray0    = nullptr;
    for (int i = 0; i < n_in; i++) {
        if      (in_sizes[i] == OUT3)                phantom = (const float*)d_in[i];
        else if (in_sizes[i] == KGRID*KGRID*KGRID*2) RI      = (const float*)d_in[i];
        else if (in_sizes[i] == NRAY2 * 5)           ray0    = (const float*)d_in[i];
    }
    float* out = (float*)d_out;

    ray_build_kernel<<<FUSED_BLOCKS, 512>>>(RI, ray0, phantom);
    sample_kernel<<<OUTN * OUTN / 8, 256>>>(out);
}